// round 1
// baseline (speedup 1.0000x reference)
#include <cuda_runtime.h>
#include <math.h>

#define NM      64
#define A_DIM   8400
#define E_DIM   128
#define NHEAD   4
#define HDIM    32
#define HWSZ    25600      // 160*160
#define LN_EPS  1e-5f
#define TABN    131072
#define XMIN    -10.0f
#define XMAX    10.0f

// ---------------- device scratch (no allocation allowed) ----------------
__device__ float g_partial[NM * 8];
__device__ float g_A1[NHEAD * NM];
__device__ float g_A2[NHEAD * NM];
__device__ float g_A3[NHEAD * NM];
__device__ float g_W [NHEAD * NM];
__device__ float g_qstat[3];          // {Vw, 2*Cwb, Vb+eps} for queries
__device__ float g_F[TABN];

// ---------------- kernel 1: prototype pooling partial sums ----------------
__global__ __launch_bounds__(256) void pool_kernel(const float* __restrict__ proto) {
    int bid = blockIdx.x;             // 0..511
    int m = bid >> 3, s = bid & 7;
    const float4* p4 = reinterpret_cast<const float4*>(proto) + m * (HWSZ / 4) + s * 800;
    float sum = 0.f;
    for (int j = threadIdx.x; j < 800; j += 256) {
        float4 v = p4[j];
        sum += (v.x + v.y) + (v.z + v.w);
    }
    // block reduce
    #pragma unroll
    for (int off = 16; off; off >>= 1) sum += __shfl_down_sync(0xffffffffu, sum, off);
    __shared__ float wsum[8];
    if ((threadIdx.x & 31) == 0) wsum[threadIdx.x >> 5] = sum;
    __syncthreads();
    if (threadIdx.x < 8) {
        float v = wsum[threadIdx.x];
        #pragma unroll
        for (int off = 4; off; off >>= 1) v += __shfl_down_sync(0xffu, v, off);
        if (threadIdx.x == 0) g_partial[bid] = v;
    }
}

// ---------------- kernel 2: precompute A1..A3, W, q-stats ----------------
__global__ __launch_bounds__(256) void precompute_kernel(
    const float* __restrict__ qw, const float* __restrict__ qb,
    const float* __restrict__ qg, const float* __restrict__ qbeta,
    const float* __restrict__ kw, const float* __restrict__ kb,
    const float* __restrict__ kg, const float* __restrict__ kbeta,
    const float* __restrict__ vw, const float* __restrict__ vb,
    const float* __restrict__ vg, const float* __restrict__ vbeta,
    const float* __restrict__ outw)
{
    __shared__ float s_pooled[NM];
    __shared__ float s_stats[15];   // q:{mw,mb,Vw,Cwb,Vb} k:{..} v:{..}
    int t = threadIdx.x;

    if (t < NM) {
        float s = 0.f;
        #pragma unroll
        for (int j = 0; j < 8; j++) s += g_partial[t * 8 + j];
        s_pooled[t] = s * (1.0f / (float)HWSZ);
    }

    if (t >= 64 && t < 96) {        // warp 2 computes the 15 moment sums
        int lane = t & 31;
        float acc[15];
        #pragma unroll
        for (int i = 0; i < 15; i++) acc[i] = 0.f;
        for (int e = lane; e < E_DIM; e += 32) {
            float a, b;
            a = qw[e]; b = qb[e];
            acc[0] += a; acc[1] += b; acc[2] += a * a; acc[3] += a * b; acc[4] += b * b;
            a = kw[e]; b = kb[e];
            acc[5] += a; acc[6] += b; acc[7] += a * a; acc[8] += a * b; acc[9] += b * b;
            a = vw[e]; b = vb[e];
            acc[10] += a; acc[11] += b; acc[12] += a * a; acc[13] += a * b; acc[14] += b * b;
        }
        #pragma unroll
        for (int off = 16; off; off >>= 1)
            #pragma unroll
            for (int i = 0; i < 15; i++) acc[i] += __shfl_down_sync(0xffffffffu, acc[i], off);
        if (lane == 0) {
            const float inv = 1.0f / (float)E_DIM;
            #pragma unroll
            for (int gidx = 0; gidx < 3; gidx++) {
                float mw  = acc[gidx * 5 + 0] * inv;
                float mb  = acc[gidx * 5 + 1] * inv;
                float Vw  = acc[gidx * 5 + 2] * inv - mw * mw;
                float Cwb = acc[gidx * 5 + 3] * inv - mw * mb;
                float Vb  = acc[gidx * 5 + 4] * inv - mb * mb;
                s_stats[gidx * 5 + 0] = mw;
                s_stats[gidx * 5 + 1] = mb;
                s_stats[gidx * 5 + 2] = Vw;
                s_stats[gidx * 5 + 3] = Cwb;
                s_stats[gidx * 5 + 4] = Vb;
            }
            g_qstat[0] = s_stats[2];
            g_qstat[1] = 2.0f * s_stats[3];
            g_qstat[2] = s_stats[4] + LN_EPS;
        }
    }
    __syncthreads();

    // thread t -> (head h, module m)
    int h = t >> 6, m = t & 63;
    float p = s_pooled[m];
    float mqw = s_stats[0],  mqb = s_stats[1];
    float mkw = s_stats[5],  mkb = s_stats[6];
    float Vkw = s_stats[7],  Ckwb = s_stats[8],  Vkb = s_stats[9];
    float mvw = s_stats[10], mvb = s_stats[11];
    float Vvw = s_stats[12], Cvwb = s_stats[13], Vvb = s_stats[14];

    float rk = rsqrtf(p * p * Vkw + 2.0f * p * Ckwb + Vkb + LN_EPS);
    float rv = rsqrtf(p * p * Vvw + 2.0f * p * Cvwb + Vvb + LN_EPS);

    float a1 = 0.f, a2 = 0.f, a3 = 0.f, w = 0.f;
    #pragma unroll 8
    for (int j = 0; j < HDIM; j++) {
        int e = h * HDIM + j;
        float ke = ((kw[e] - mkw) * p + (kb[e] - mkb)) * rk * kg[e] + kbeta[e];
        float ve = ((vw[e] - mvw) * p + (vb[e] - mvb)) * rv * vg[e] + vbeta[e];
        float uq = (qw[e] - mqw) * qg[e];
        float tq = (qb[e] - mqb) * qg[e];
        a1 = fmaf(uq, ke, a1);
        a2 = fmaf(tq, ke, a2);
        a3 = fmaf(qbeta[e], ke, a3);
        w  = fmaf(ve, outw[e], w);
    }
    float scale = rsqrtf((float)HDIM);
    g_A1[t] = a1 * scale;
    g_A2[t] = a2 * scale;
    g_A3[t] = a3 * scale;
    g_W[t]  = w;
}

// ---------------- shared evaluator: refined = F(x) ----------------
__device__ __forceinline__ float eval_F(float x,
    const float* __restrict__ A1, const float* __restrict__ A2,
    const float* __restrict__ A3, const float* __restrict__ W,
    float qa, float qb2, float qc, float out_b)
{
    // r(x) = rsqrt(Vw*x^2 + 2Cwb*x + Vb + eps)
    float r = rsqrtf(fmaf(x, fmaf(qa, x, qb2), qc));
    float acc = out_b;
    #pragma unroll
    for (int h = 0; h < NHEAD; h++) {
        const float* A1h = A1 + h * NM;
        const float* A2h = A2 + h * NM;
        const float* A3h = A3 + h * NM;
        const float* Wh  = W  + h * NM;
        float mx = -1e30f;
        #pragma unroll 8
        for (int m = 0; m < NM; m++) {
            float s = fmaf(r, fmaf(x, A1h[m], A2h[m]), A3h[m]);
            mx = fmaxf(mx, s);
        }
        float se = 0.f, ws = 0.f;
        #pragma unroll 8
        for (int m = 0; m < NM; m++) {
            float s = fmaf(r, fmaf(x, A1h[m], A2h[m]), A3h[m]);
            float e = __expf(s - mx);
            se += e;
            ws = fmaf(e, Wh[m], ws);
        }
        acc += __fdividef(ws, se);
    }
    return acc;
}

// ---------------- kernel 3: tabulate F on a dense grid ----------------
__global__ __launch_bounds__(256) void table_kernel(const float* __restrict__ outb) {
    __shared__ float sA1[NHEAD * NM], sA2[NHEAD * NM], sA3[NHEAD * NM], sW[NHEAD * NM];
    int t = threadIdx.x;
    sA1[t] = g_A1[t]; sA2[t] = g_A2[t]; sA3[t] = g_A3[t]; sW[t] = g_W[t];
    __syncthreads();
    int i = blockIdx.x * 256 + t;
    double hstep = (double)((double)XMAX - (double)XMIN) / (double)(TABN - 1);
    float x = (float)((double)XMIN + (double)i * hstep);
    g_F[i] = eval_F(x, sA1, sA2, sA3, sW, g_qstat[0], g_qstat[1], g_qstat[2], outb[0]);
}

// ---------------- kernel 4: pointwise apply (lerp + gate) ----------------
__global__ __launch_bounds__(256) void apply_kernel(
    const float* __restrict__ coeff, float* __restrict__ out,
    const float* __restrict__ gatew, const float* __restrict__ gateb,
    const float* __restrict__ outb)
{
    int i = blockIdx.x * 256 + threadIdx.x;     // 0..134399 (float4 index)
    float4 xv = reinterpret_cast<const float4*>(coeff)[i];
    float gw0 = gatew[0], gw1 = gatew[1], gbv = gateb[0];

    const double INVH = (double)(TABN - 1) / ((double)XMAX - (double)XMIN);
    float xin[4] = {xv.x, xv.y, xv.z, xv.w};
    float res[4];
    #pragma unroll
    for (int j = 0; j < 4; j++) {
        float x = xin[j];
        float F;
        if (x >= XMIN && x <= XMAX) {
            double td = ((double)x - (double)XMIN) * INVH;
            int i0 = (int)td;
            if (i0 > TABN - 2) i0 = TABN - 2;
            float f = (float)(td - (double)i0);
            float f0 = g_F[i0];
            float f1 = g_F[i0 + 1];
            F = fmaf(f, f1 - f0, f0);
        } else {
            F = eval_F(x, g_A1, g_A2, g_A3, g_W,
                       g_qstat[0], g_qstat[1], g_qstat[2], outb[0]);
        }
        float z = fmaf(gw1, F, fmaf(gw0, x, gbv));
        float g = __fdividef(1.0f, 1.0f + __expf(-z));
        res[j] = fmaf(g, F - x, x);   // g*F + (1-g)*x
    }
    float4 ov = {res[0], res[1], res[2], res[3]};
    reinterpret_cast<float4*>(out)[i] = ov;
}

// ---------------- launch ----------------
extern "C" void kernel_launch(void* const* d_in, const int* in_sizes, int n_in,
                              void* d_out, int out_size) {
    (void)in_sizes; (void)n_in; (void)out_size;
    const float* coeff = (const float*)d_in[0];
    const float* proto = (const float*)d_in[1];
    const float* qw    = (const float*)d_in[2];
    const float* qb    = (const float*)d_in[3];
    const float* qg    = (const float*)d_in[4];
    const float* qbeta = (const float*)d_in[5];
    const float* kw    = (const float*)d_in[6];
    const float* kb    = (const float*)d_in[7];
    const float* kg    = (const float*)d_in[8];
    const float* kbeta = (const float*)d_in[9];
    const float* vw    = (const float*)d_in[10];
    const float* vb    = (const float*)d_in[11];
    const float* vg    = (const float*)d_in[12];
    const float* vbeta = (const float*)d_in[13];
    const float* outw  = (const float*)d_in[14];
    const float* outb  = (const float*)d_in[15];
    const float* gatew = (const float*)d_in[16];
    const float* gateb = (const float*)d_in[17];
    float* out = (float*)d_out;

    pool_kernel<<<512, 256>>>(proto);
    precompute_kernel<<<1, 256>>>(qw, qb, qg, qbeta, kw, kb, kg, kbeta,
                                  vw, vb, vg, vbeta, outw);
    table_kernel<<<TABN / 256, 256>>>(outb);
    apply_kernel<<<(NM * A_DIM / 4) / 256, 256>>>(coeff, out, gatew, gateb, outb);
}

// round 2
// speedup vs baseline: 1.5594x; 1.5594x over previous
#include <cuda_runtime.h>
#include <math.h>

#define NM      64
#define A_DIM   8400
#define E_DIM   128
#define NHEAD   4
#define HDIM    32
#define HWSZ    25600      // 160*160
#define LN_EPS  1e-5f
#define TABN    16384
#define TPB     256
#define TAB_BLOCKS (TABN / TPB)     // 64
#define XMIN    -10.0f
#define XMAX    10.0f

// ---------------- device scratch (no allocation allowed) ----------------
__device__ float  g_partial[NM * 8];
__device__ float  g_A1[NHEAD * NM];
__device__ float  g_A2[NHEAD * NM];
__device__ float  g_A3[NHEAD * NM];
__device__ float  g_W [NHEAD * NM];
__device__ float  g_qstat[3];          // {Vw, 2*Cwb, Vb+eps} for queries
__device__ float2 g_F2[TABN];          // (F[i], F[i+1]) pairs

// ---------------- kernel 1: prototype pooling partial sums ----------------
__global__ __launch_bounds__(256) void pool_kernel(const float* __restrict__ proto) {
    int bid = blockIdx.x;             // 0..511
    int m = bid >> 3, s = bid & 7;
    const float4* p4 = reinterpret_cast<const float4*>(proto) + m * (HWSZ / 4) + s * 800;
    float sum = 0.f;
    for (int j = threadIdx.x; j < 800; j += 256) {
        float4 v = p4[j];
        sum += (v.x + v.y) + (v.z + v.w);
    }
    #pragma unroll
    for (int off = 16; off; off >>= 1) sum += __shfl_down_sync(0xffffffffu, sum, off);
    __shared__ float wsum[8];
    if ((threadIdx.x & 31) == 0) wsum[threadIdx.x >> 5] = sum;
    __syncthreads();
    if (threadIdx.x < 8) {
        float v = wsum[threadIdx.x];
        #pragma unroll
        for (int off = 4; off; off >>= 1) v += __shfl_down_sync(0xffu, v, off);
        if (threadIdx.x == 0) g_partial[bid] = v;
    }
}

// ---------------- shared evaluator: refined = F(x) ----------------
__device__ __forceinline__ float eval_F(float x,
    const float* __restrict__ A1, const float* __restrict__ A2,
    const float* __restrict__ A3, const float* __restrict__ W,
    float qa, float qb2, float qc, float out_b)
{
    float r = rsqrtf(fmaf(x, fmaf(qa, x, qb2), qc));
    float acc = out_b;
    #pragma unroll
    for (int h = 0; h < NHEAD; h++) {
        const float* A1h = A1 + h * NM;
        const float* A2h = A2 + h * NM;
        const float* A3h = A3 + h * NM;
        const float* Wh  = W  + h * NM;
        float mx = -1e30f;
        #pragma unroll 8
        for (int m = 0; m < NM; m++) {
            float s = fmaf(r, fmaf(x, A1h[m], A2h[m]), A3h[m]);
            mx = fmaxf(mx, s);
        }
        float se = 0.f, ws = 0.f;
        #pragma unroll 8
        for (int m = 0; m < NM; m++) {
            float s = fmaf(r, fmaf(x, A1h[m], A2h[m]), A3h[m]);
            float e = __expf(s - mx);
            se += e;
            ws = fmaf(e, Wh[m], ws);
        }
        acc += __fdividef(ws, se);
    }
    return acc;
}

// ---------- kernel 2 (fused): per-block precompute + table slice ----------
__global__ __launch_bounds__(TPB) void table_kernel(
    const float* __restrict__ qw, const float* __restrict__ qb,
    const float* __restrict__ qg, const float* __restrict__ qbeta,
    const float* __restrict__ kw, const float* __restrict__ kb,
    const float* __restrict__ kg, const float* __restrict__ kbeta,
    const float* __restrict__ vw, const float* __restrict__ vb,
    const float* __restrict__ vg, const float* __restrict__ vbeta,
    const float* __restrict__ outw, const float* __restrict__ outb)
{
    __shared__ float s_pooled[NM];
    __shared__ float s_stats[15];   // q:{mw,mb,Vw,Cwb,Vb} k:{..} v:{..}
    __shared__ float sA1[NHEAD * NM], sA2[NHEAD * NM], sA3[NHEAD * NM], sW[NHEAD * NM];
    __shared__ float sF[TPB + 1];
    int t = threadIdx.x;

    if (t < NM) {
        float s = 0.f;
        #pragma unroll
        for (int j = 0; j < 8; j++) s += g_partial[t * 8 + j];
        s_pooled[t] = s * (1.0f / (float)HWSZ);
    }

    if (t >= 64 && t < 96) {        // warp 2 computes the 15 moment sums
        int lane = t & 31;
        float acc[15];
        #pragma unroll
        for (int i = 0; i < 15; i++) acc[i] = 0.f;
        for (int e = lane; e < E_DIM; e += 32) {
            float a, b;
            a = qw[e]; b = qb[e];
            acc[0] += a; acc[1] += b; acc[2] += a * a; acc[3] += a * b; acc[4] += b * b;
            a = kw[e]; b = kb[e];
            acc[5] += a; acc[6] += b; acc[7] += a * a; acc[8] += a * b; acc[9] += b * b;
            a = vw[e]; b = vb[e];
            acc[10] += a; acc[11] += b; acc[12] += a * a; acc[13] += a * b; acc[14] += b * b;
        }
        #pragma unroll
        for (int off = 16; off; off >>= 1)
            #pragma unroll
            for (int i = 0; i < 15; i++) acc[i] += __shfl_down_sync(0xffffffffu, acc[i], off);
        if (lane == 0) {
            const float inv = 1.0f / (float)E_DIM;
            #pragma unroll
            for (int gidx = 0; gidx < 3; gidx++) {
                float mw  = acc[gidx * 5 + 0] * inv;
                float mb  = acc[gidx * 5 + 1] * inv;
                s_stats[gidx * 5 + 0] = mw;
                s_stats[gidx * 5 + 1] = mb;
                s_stats[gidx * 5 + 2] = acc[gidx * 5 + 2] * inv - mw * mw;
                s_stats[gidx * 5 + 3] = acc[gidx * 5 + 3] * inv - mw * mb;
                s_stats[gidx * 5 + 4] = acc[gidx * 5 + 4] * inv - mb * mb;
            }
        }
    }
    __syncthreads();

    float qa  = s_stats[2];
    float qb2 = 2.0f * s_stats[3];
    float qc  = s_stats[4] + LN_EPS;
    if (blockIdx.x == 0 && t == 0) {
        g_qstat[0] = qa; g_qstat[1] = qb2; g_qstat[2] = qc;
    }

    // thread t -> (head h, module m)
    {
        int h = t >> 6, m = t & 63;
        float p = s_pooled[m];
        float mqw = s_stats[0],  mqb = s_stats[1];
        float mkw = s_stats[5],  mkb = s_stats[6];
        float Vkw = s_stats[7],  Ckwb = s_stats[8],  Vkb = s_stats[9];
        float mvw = s_stats[10], mvb = s_stats[11];
        float Vvw = s_stats[12], Cvwb = s_stats[13], Vvb = s_stats[14];

        float rk = rsqrtf(p * p * Vkw + 2.0f * p * Ckwb + Vkb + LN_EPS);
        float rv = rsqrtf(p * p * Vvw + 2.0f * p * Cvwb + Vvb + LN_EPS);

        float a1 = 0.f, a2 = 0.f, a3 = 0.f, w = 0.f;
        #pragma unroll 8
        for (int j = 0; j < HDIM; j++) {
            int e = h * HDIM + j;
            float ke = ((kw[e] - mkw) * p + (kb[e] - mkb)) * rk * kg[e] + kbeta[e];
            float ve = ((vw[e] - mvw) * p + (vb[e] - mvb)) * rv * vg[e] + vbeta[e];
            float uq = (qw[e] - mqw) * qg[e];
            float tq = (qb[e] - mqb) * qg[e];
            a1 = fmaf(uq, ke, a1);
            a2 = fmaf(tq, ke, a2);
            a3 = fmaf(qbeta[e], ke, a3);
            w  = fmaf(ve, outw[e], w);
        }
        float scale = rsqrtf((float)HDIM);
        sA1[t] = a1 * scale;
        sA2[t] = a2 * scale;
        sA3[t] = a3 * scale;
        sW[t]  = w;
        if (blockIdx.x == 0) {
            g_A1[t] = sA1[t]; g_A2[t] = sA2[t]; g_A3[t] = sA3[t]; g_W[t] = sW[t];
        }
    }
    __syncthreads();

    const float hstep = (XMAX - XMIN) / (float)(TABN - 1);
    float ob = outb[0];
    int base = blockIdx.x * TPB;
    float x = XMIN + (float)(base + t) * hstep;
    sF[t] = eval_F(x, sA1, sA2, sA3, sW, qa, qb2, qc, ob);
    if (t == 0) {
        // extra node for the pair at the block boundary (clamped at the end)
        int ie = base + TPB;
        float xe = (ie < TABN) ? (XMIN + (float)ie * hstep) : XMAX;
        sF[TPB] = eval_F(xe, sA1, sA2, sA3, sW, qa, qb2, qc, ob);
    }
    __syncthreads();
    g_F2[base + t] = make_float2(sF[t], sF[t + 1]);
}

// ---------------- kernel 3: pointwise apply (lerp + gate) ----------------
#define APPLY_V4_PER_THREAD 3
#define APPLY_BLOCKS 175            // 175 * 256 * 3 = 134400 float4 = 537600

__global__ __launch_bounds__(256) void apply_kernel(
    const float* __restrict__ coeff, float* __restrict__ out,
    const float* __restrict__ gatew, const float* __restrict__ gateb,
    const float* __restrict__ outb)
{
    int tid = blockIdx.x * 256 + threadIdx.x;
    const float4* cin = reinterpret_cast<const float4*>(coeff);
    float4* cout = reinterpret_cast<float4*>(out);
    float gw0 = __ldg(gatew), gw1 = __ldg(gatew + 1), gbv = __ldg(gateb);

    const float INVH = (float)(TABN - 1) / (XMAX - XMIN);
    const int NTHREADS = APPLY_BLOCKS * 256;

    float4 xv[APPLY_V4_PER_THREAD];
    #pragma unroll
    for (int v = 0; v < APPLY_V4_PER_THREAD; v++)
        xv[v] = cin[tid + v * NTHREADS];

    #pragma unroll
    for (int v = 0; v < APPLY_V4_PER_THREAD; v++) {
        float xin[4] = {xv[v].x, xv[v].y, xv[v].z, xv[v].w};
        float res[4];
        #pragma unroll
        for (int j = 0; j < 4; j++) {
            float x = xin[j];
            float F;
            if (x >= XMIN && x <= XMAX) {
                float tpos = (x - XMIN) * INVH;
                int i0 = (int)tpos;
                if (i0 > TABN - 2) i0 = TABN - 2;
                float f = tpos - (float)i0;
                float2 p = g_F2[i0];
                F = fmaf(f, p.y - p.x, p.x);
            } else {
                F = eval_F(x, g_A1, g_A2, g_A3, g_W,
                           g_qstat[0], g_qstat[1], g_qstat[2], __ldg(outb));
            }
            float z = fmaf(gw1, F, fmaf(gw0, x, gbv));
            float g = __fdividef(1.0f, 1.0f + __expf(-z));
            res[j] = fmaf(g, F - x, x);   // g*F + (1-g)*x
        }
        float4 ov = {res[0], res[1], res[2], res[3]};
        cout[tid + v * NTHREADS] = ov;
    }
}

// ---------------- launch ----------------
extern "C" void kernel_launch(void* const* d_in, const int* in_sizes, int n_in,
                              void* d_out, int out_size) {
    (void)in_sizes; (void)n_in; (void)out_size;
    const float* coeff = (const float*)d_in[0];
    const float* proto = (const float*)d_in[1];
    const float* qw    = (const float*)d_in[2];
    const float* qb    = (const float*)d_in[3];
    const float* qg    = (const float*)d_in[4];
    const float* qbeta = (const float*)d_in[5];
    const float* kw    = (const float*)d_in[6];
    const float* kb    = (const float*)d_in[7];
    const float* kg    = (const float*)d_in[8];
    const float* kbeta = (const float*)d_in[9];
    const float* vw    = (const float*)d_in[10];
    const float* vb    = (const float*)d_in[11];
    const float* vg    = (const float*)d_in[12];
    const float* vbeta = (const float*)d_in[13];
    const float* outw  = (const float*)d_in[14];
    const float* outb  = (const float*)d_in[15];
    const float* gatew = (const float*)d_in[16];
    const float* gateb = (const float*)d_in[17];
    float* out = (float*)d_out;

    pool_kernel<<<512, 256>>>(proto);
    table_kernel<<<TAB_BLOCKS, TPB>>>(qw, qb, qg, qbeta, kw, kb, kg, kbeta,
                                      vw, vb, vg, vbeta, outw, outb);
    apply_kernel<<<APPLY_BLOCKS, 256>>>(coeff, out, gatew, gateb, outb);
}

// round 3
// speedup vs baseline: 2.3308x; 1.4947x over previous
#include <cuda_runtime.h>
#include <math.h>

#define NM      64
#define A_DIM   8400
#define E_DIM   128
#define NHEAD   4
#define HDIM    32
#define HWSZ    25600      // 160*160
#define LN_EPS  1e-5f
#define LOG2E   1.4426950408889634f
#define TABN    16384
#define XMIN    -10.0f
#define XMAX    10.0f

#define POOL_BLOCKS 320     // 5 segments per module, 1280 float4 each
#define TAB_TPB     128
#define TAB_BLOCKS  129     // 127 usable nodes per block (overlap by 1)

// ---------------- device scratch (no allocation allowed) ----------------
__device__ float  g_partial[POOL_BLOCKS];
__device__ float4 g_AB[NHEAD * NM];    // (A1,A2,A3,W) per (head,module); A* pre-scaled by log2e
__device__ float  g_qstat[3];          // {Vw, 2*Cwb, Vb+eps} for queries
__device__ float2 g_F2[TABN];          // (F[i], F[i+1]) pairs

__device__ __forceinline__ float fast_ex2(float x) {
    float y; asm("ex2.approx.f32 %0, %1;" : "=f"(y) : "f"(x)); return y;
}

// ---------------- kernel 1: prototype pooling partial sums ----------------
__global__ __launch_bounds__(256) void pool_kernel(const float* __restrict__ proto) {
    const float4* p4 = reinterpret_cast<const float4*>(proto) + (size_t)blockIdx.x * 1280;
    int t = threadIdx.x;
    float4 v[5];
    #pragma unroll
    for (int k = 0; k < 5; k++) v[k] = p4[t + k * 256];
    float sum = 0.f;
    #pragma unroll
    for (int k = 0; k < 5; k++) sum += (v[k].x + v[k].y) + (v[k].z + v[k].w);
    #pragma unroll
    for (int off = 16; off; off >>= 1) sum += __shfl_down_sync(0xffffffffu, sum, off);
    __shared__ float wsum[8];
    if ((t & 31) == 0) wsum[t >> 5] = sum;
    __syncthreads();
    if (t < 8) {
        float v2 = wsum[t];
        #pragma unroll
        for (int off = 4; off; off >>= 1) v2 += __shfl_down_sync(0xffu, v2, off);
        if (t == 0) g_partial[blockIdx.x] = v2;
    }
}

// ---------------- shared evaluator: refined = F(x) ----------------
// AB holds (A1*log2e*scale, A2*log2e*scale, A3*log2e*scale, W)
template <bool INLINE_HINT>
__device__ __forceinline__ float eval_F_impl(float x, const float4* __restrict__ AB,
                                             float qa, float qb2, float qc, float out_b)
{
    float r = rsqrtf(fmaf(x, fmaf(qa, x, qb2), qc));
    float acc = out_b;
    #pragma unroll
    for (int h = 0; h < NHEAD; h++) {
        const float4* ABh = AB + h * NM;
        float s[NM];
        float mx = -1e30f;
        #pragma unroll
        for (int m = 0; m < NM; m++) {
            float4 ab = ABh[m];
            s[m] = fmaf(r, fmaf(x, ab.x, ab.y), ab.z);
            mx = fmaxf(mx, s[m]);
        }
        float se = 0.f, ws = 0.f;
        #pragma unroll
        for (int m = 0; m < NM; m++) {
            float4 ab = ABh[m];
            float e = fast_ex2(s[m] - mx);
            se += e;
            ws = fmaf(e, ab.w, ws);
        }
        acc += __fdividef(ws, se);
    }
    return acc;
}

__device__ __noinline__ float eval_F_cold(float x, float qa, float qb2, float qc, float out_b)
{
    return eval_F_impl<false>(x, g_AB, qa, qb2, qc, out_b);
}

// ---------- kernel 2 (fused): per-block precompute + table slice ----------
__global__ __launch_bounds__(TAB_TPB) void table_kernel(
    const float* __restrict__ qw, const float* __restrict__ qb,
    const float* __restrict__ qg, const float* __restrict__ qbeta,
    const float* __restrict__ kw, const float* __restrict__ kb,
    const float* __restrict__ kg, const float* __restrict__ kbeta,
    const float* __restrict__ vw, const float* __restrict__ vb,
    const float* __restrict__ vg, const float* __restrict__ vbeta,
    const float* __restrict__ outw, const float* __restrict__ outb)
{
    __shared__ float  s_pooled[NM];
    __shared__ float  s_stats[15];   // q:{mw,mb,Vw,Cwb,Vb} k:{..} v:{..}
    __shared__ float4 s_k[E_DIM];    // (kw,kb,kg,kbeta)
    __shared__ float4 s_v[E_DIM];    // (vw,vb,vg,vbeta)
    __shared__ float4 s_q[E_DIM];    // (qw,qb,qg,qbeta)
    __shared__ float  s_ow[E_DIM];
    __shared__ float4 sAB[NHEAD * NM];
    __shared__ float  sF[TAB_TPB + 1];
    int t = threadIdx.x;

    // stage param tuples into shared (each thread covers index t only: E=128=TPB)
    s_k[t] = make_float4(kw[t], kb[t], kg[t], kbeta[t]);
    s_v[t] = make_float4(vw[t], vb[t], vg[t], vbeta[t]);
    s_q[t] = make_float4(qw[t], qb[t], qg[t], qbeta[t]);
    s_ow[t] = outw[t];

    if (t < NM) {
        float s = 0.f;
        #pragma unroll
        for (int j = 0; j < 5; j++) s += g_partial[t * 5 + j];
        s_pooled[t] = s * (1.0f / (float)HWSZ);
    }

    if (t >= 64 && t < 96) {        // warp 2 computes the 15 moment sums
        int lane = t & 31;
        float acc[15];
        #pragma unroll
        for (int i = 0; i < 15; i++) acc[i] = 0.f;
        #pragma unroll
        for (int rep = 0; rep < 4; rep++) {
            int e = lane + rep * 32;
            float a, b;
            a = qw[e]; b = qb[e];
            acc[0] += a; acc[1] += b; acc[2] += a * a; acc[3] += a * b; acc[4] += b * b;
            a = kw[e]; b = kb[e];
            acc[5] += a; acc[6] += b; acc[7] += a * a; acc[8] += a * b; acc[9] += b * b;
            a = vw[e]; b = vb[e];
            acc[10] += a; acc[11] += b; acc[12] += a * a; acc[13] += a * b; acc[14] += b * b;
        }
        #pragma unroll
        for (int off = 16; off; off >>= 1)
            #pragma unroll
            for (int i = 0; i < 15; i++) acc[i] += __shfl_down_sync(0xffffffffu, acc[i], off);
        if (lane == 0) {
            const float inv = 1.0f / (float)E_DIM;
            #pragma unroll
            for (int gidx = 0; gidx < 3; gidx++) {
                float mw  = acc[gidx * 5 + 0] * inv;
                float mb  = acc[gidx * 5 + 1] * inv;
                s_stats[gidx * 5 + 0] = mw;
                s_stats[gidx * 5 + 1] = mb;
                s_stats[gidx * 5 + 2] = acc[gidx * 5 + 2] * inv - mw * mw;
                s_stats[gidx * 5 + 3] = acc[gidx * 5 + 3] * inv - mw * mb;
                s_stats[gidx * 5 + 4] = acc[gidx * 5 + 4] * inv - mb * mb;
            }
        }
    }
    __syncthreads();

    float qa  = s_stats[2];
    float qb2 = 2.0f * s_stats[3];
    float qc  = s_stats[4] + LN_EPS;
    if (blockIdx.x == 0 && t == 0) {
        g_qstat[0] = qa; g_qstat[1] = qb2; g_qstat[2] = qc;
    }

    // each thread computes 2 (head,module) coefficient entries
    {
        float mqw = s_stats[0],  mqb = s_stats[1];
        float mkw = s_stats[5],  mkb = s_stats[6];
        float Vkw = s_stats[7],  Ckwb = s_stats[8],  Vkb = s_stats[9];
        float mvw = s_stats[10], mvb = s_stats[11];
        float Vvw = s_stats[12], Cvwb = s_stats[13], Vvb = s_stats[14];
        const float cscale = rsqrtf((float)HDIM) * LOG2E;

        #pragma unroll
        for (int rep = 0; rep < 2; rep++) {
            int idx = t + rep * TAB_TPB;           // 0..255
            int h = idx >> 6, m = idx & 63;
            float p = s_pooled[m];
            float rk = rsqrtf(p * p * Vkw + 2.0f * p * Ckwb + Vkb + LN_EPS);
            float rv = rsqrtf(p * p * Vvw + 2.0f * p * Cvwb + Vvb + LN_EPS);

            float a1 = 0.f, a2 = 0.f, a3 = 0.f, w = 0.f;
            #pragma unroll 8
            for (int j = 0; j < HDIM; j++) {
                int e = h * HDIM + j;
                float4 kk = s_k[e];
                float4 vv = s_v[e];
                float4 qq = s_q[e];
                float ke = ((kk.x - mkw) * p + (kk.y - mkb)) * rk * kk.z + kk.w;
                float ve = ((vv.x - mvw) * p + (vv.y - mvb)) * rv * vv.z + vv.w;
                float uq = (qq.x - mqw) * qq.z;
                float tq = (qq.y - mqb) * qq.z;
                a1 = fmaf(uq, ke, a1);
                a2 = fmaf(tq, ke, a2);
                a3 = fmaf(qq.w, ke, a3);
                w  = fmaf(ve, s_ow[e], w);
            }
            float4 out4 = make_float4(a1 * cscale, a2 * cscale, a3 * cscale, w);
            sAB[idx] = out4;
            if (blockIdx.x == 0) g_AB[idx] = out4;
        }
    }
    __syncthreads();

    const float hstep = (XMAX - XMIN) / (float)(TABN - 1);
    float ob = outb[0];
    int base = blockIdx.x * (TAB_TPB - 1);          // blocks overlap by 1 node
    int i = base + t;                                // max = 128*127+127 = 16383
    float x = XMIN + (float)i * hstep;
    sF[t] = eval_F_impl<true>(x, sAB, qa, qb2, qc, ob);
    __syncthreads();
    if (t < TAB_TPB - 1)
        g_F2[base + t] = make_float2(sF[t], sF[t + 1]);
}

// ---------------- kernel 3: pointwise apply (lerp + gate) ----------------
#define APPLY_V4_PER_THREAD 3
#define APPLY_BLOCKS 175            // 175 * 256 * 3 = 134400 float4 = 537600

__global__ __launch_bounds__(256) void apply_kernel(
    const float* __restrict__ coeff, float* __restrict__ out,
    const float* __restrict__ gatew, const float* __restrict__ gateb,
    const float* __restrict__ outb)
{
    int tid = blockIdx.x * 256 + threadIdx.x;
    const float4* cin = reinterpret_cast<const float4*>(coeff);
    float4* cout = reinterpret_cast<float4*>(out);
    float gw0 = __ldg(gatew), gw1 = __ldg(gatew + 1), gbv = __ldg(gateb);

    const float INVH = (float)(TABN - 1) / (XMAX - XMIN);
    const int NTHREADS = APPLY_BLOCKS * 256;

    float4 xv[APPLY_V4_PER_THREAD];
    #pragma unroll
    for (int v = 0; v < APPLY_V4_PER_THREAD; v++)
        xv[v] = cin[tid + v * NTHREADS];

    #pragma unroll
    for (int v = 0; v < APPLY_V4_PER_THREAD; v++) {
        float xin[4] = {xv[v].x, xv[v].y, xv[v].z, xv[v].w};
        float res[4];
        #pragma unroll
        for (int j = 0; j < 4; j++) {
            float x = xin[j];
            float F;
            if (x >= XMIN && x <= XMAX) {
                float tpos = (x - XMIN) * INVH;
                int i0 = (int)tpos;
                if (i0 > TABN - 2) i0 = TABN - 2;
                float f = tpos - (float)i0;
                float2 p = g_F2[i0];
                F = fmaf(f, p.y - p.x, p.x);
            } else {
                F = eval_F_cold(x, g_qstat[0], g_qstat[1], g_qstat[2], __ldg(outb));
            }
            float z = fmaf(gw1, F, fmaf(gw0, x, gbv));
            float g = __fdividef(1.0f, 1.0f + __expf(-z));
            res[j] = fmaf(g, F - x, x);   // g*F + (1-g)*x
        }
        float4 ov = {res[0], res[1], res[2], res[3]};
        cout[tid + v * NTHREADS] = ov;
    }
}

// ---------------- launch ----------------
extern "C" void kernel_launch(void* const* d_in, const int* in_sizes, int n_in,
                              void* d_out, int out_size) {
    (void)in_sizes; (void)n_in; (void)out_size;
    const float* coeff = (const float*)d_in[0];
    const float* proto = (const float*)d_in[1];
    const float* qw    = (const float*)d_in[2];
    const float* qb    = (const float*)d_in[3];
    const float* qg    = (const float*)d_in[4];
    const float* qbeta = (const float*)d_in[5];
    const float* kw    = (const float*)d_in[6];
    const float* kb    = (const float*)d_in[7];
    const float* kg    = (const float*)d_in[8];
    const float* kbeta = (const float*)d_in[9];
    const float* vw    = (const float*)d_in[10];
    const float* vb    = (const float*)d_in[11];
    const float* vg    = (const float*)d_in[12];
    const float* vbeta = (const float*)d_in[13];
    const float* outw  = (const float*)d_in[14];
    const float* outb  = (const float*)d_in[15];
    const float* gatew = (const float*)d_in[16];
    const float* gateb = (const float*)d_in[17];
    float* out = (float*)d_out;

    pool_kernel<<<POOL_BLOCKS, 256>>>(proto);
    table_kernel<<<TAB_BLOCKS, TAB_TPB>>>(qw, qb, qg, qbeta, kw, kb, kg, kbeta,
                                          vw, vb, vg, vbeta, outw, outb);
    apply_kernel<<<APPLY_BLOCKS, 256>>>(coeff, out, gatew, gateb, outb);
}

// round 4
// speedup vs baseline: 2.4257x; 1.0407x over previous
#include <cuda_runtime.h>
#include <math.h>

#define NM      64
#define A_DIM   8400
#define E_DIM   128
#define NHEAD   4
#define HDIM    32
#define HWSZ    25600      // 160*160
#define LN_EPS  1e-5f
#define LOG2E   1.4426950408889634f
#define TABN    8192
#define XMIN    -10.0f
#define XMAX    10.0f

#define POOL_BLOCKS 128     // 2 blocks per module, 3200 float4 each, 320 thr x 10 f4
#define POOL_TPB    320
#define TAB_TPB     128
#define TAB_BLOCKS  65      // 127 usable nodes per block (overlap by 1)

#define APPLY_BLOCKS 148
#define APPLY_TPB    256
#define APPLY_NT     (APPLY_BLOCKS * APPLY_TPB)   // 37888
#define APPLY_NV4    (NM * A_DIM / 4)             // 134400

// ---------------- device scratch (no allocation allowed) ----------------
__device__ float  g_partial[POOL_BLOCKS];
__device__ float4 g_AB[NHEAD * NM];    // (A1,A2,A3,W); A* pre-scaled by log2e*scale
__device__ float  g_qstat[3];          // {Vw, 2*Cwb, Vb+eps} for queries
__device__ float2 g_F2[TABN];          // (F[i], F[i+1]) pairs

__device__ __forceinline__ float fast_ex2(float x) {
    float y; asm("ex2.approx.f32 %0, %1;" : "=f"(y) : "f"(x)); return y;
}

// ---------------- kernel 1: prototype pooling partial sums ----------------
__global__ __launch_bounds__(POOL_TPB) void pool_kernel(const float* __restrict__ proto) {
    const float4* p4 = reinterpret_cast<const float4*>(proto) + (size_t)blockIdx.x * 3200;
    int t = threadIdx.x;
    float4 v[10];
    #pragma unroll
    for (int k = 0; k < 10; k++) v[k] = p4[t + k * POOL_TPB];
    float sum = 0.f;
    #pragma unroll
    for (int k = 0; k < 10; k++) sum += (v[k].x + v[k].y) + (v[k].z + v[k].w);
    #pragma unroll
    for (int off = 16; off; off >>= 1) sum += __shfl_down_sync(0xffffffffu, sum, off);
    __shared__ float wsum[10];
    if ((t & 31) == 0) wsum[t >> 5] = sum;
    __syncthreads();
    if (t < 16) {
        float v2 = (t < 10) ? wsum[t] : 0.f;
        #pragma unroll
        for (int off = 8; off; off >>= 1) v2 += __shfl_down_sync(0xffffu, v2, off);
        if (t == 0) g_partial[blockIdx.x] = v2;
    }
}

// ---------------- shared evaluator: refined = F(x) ----------------
// AB holds (A1*log2e*scale, A2*log2e*scale, A3*log2e*scale, W)
__device__ __forceinline__ float eval_F_impl(float x, const float4* __restrict__ AB,
                                             float qa, float qb2, float qc, float out_b)
{
    float r = rsqrtf(fmaf(x, fmaf(qa, x, qb2), qc));
    float acc = out_b;
    #pragma unroll
    for (int h = 0; h < NHEAD; h++) {
        const float4* ABh = AB + h * NM;
        float s[NM];
        float mx = -1e30f;
        #pragma unroll
        for (int m = 0; m < NM; m++) {
            float4 ab = ABh[m];
            s[m] = fmaf(r, fmaf(x, ab.x, ab.y), ab.z);
            mx = fmaxf(mx, s[m]);
        }
        float se = 0.f, ws = 0.f;
        #pragma unroll
        for (int m = 0; m < NM; m++) {
            float4 ab = ABh[m];
            float e = fast_ex2(s[m] - mx);
            se += e;
            ws = fmaf(e, ab.w, ws);
        }
        acc += __fdividef(ws, se);
    }
    return acc;
}

__device__ __noinline__ float eval_F_cold(float x, float qa, float qb2, float qc, float out_b)
{
    return eval_F_impl(x, g_AB, qa, qb2, qc, out_b);
}

// ---------- kernel 2 (fused): per-block precompute + table slice ----------
__global__ __launch_bounds__(TAB_TPB) void table_kernel(
    const float* __restrict__ qw, const float* __restrict__ qb,
    const float* __restrict__ qg, const float* __restrict__ qbeta,
    const float* __restrict__ kw, const float* __restrict__ kb,
    const float* __restrict__ kg, const float* __restrict__ kbeta,
    const float* __restrict__ vw, const float* __restrict__ vb,
    const float* __restrict__ vg, const float* __restrict__ vbeta,
    const float* __restrict__ outw, const float* __restrict__ outb)
{
    __shared__ float  s_pooled[NM];
    __shared__ float  s_stats[15];   // q:{mw,mb,Vw,Cwb,Vb} k:{..} v:{..}
    __shared__ float4 s_k[E_DIM];    // (kw,kb,kg,kbeta)
    __shared__ float4 s_v[E_DIM];    // (vw,vb,vg,vbeta)
    __shared__ float4 s_q[E_DIM];    // (qw,qb,qg,qbeta)
    __shared__ float  s_ow[E_DIM];
    __shared__ float4 sAB[NHEAD * NM];
    __shared__ float  sF[TAB_TPB + 1];
    int t = threadIdx.x;

    // stage param tuples into shared (E = 128 = TPB)
    s_k[t] = make_float4(kw[t], kb[t], kg[t], kbeta[t]);
    s_v[t] = make_float4(vw[t], vb[t], vg[t], vbeta[t]);
    s_q[t] = make_float4(qw[t], qb[t], qg[t], qbeta[t]);
    s_ow[t] = outw[t];

    if (t < NM) {
        float s = g_partial[2 * t] + g_partial[2 * t + 1];
        s_pooled[t] = s * (1.0f / (float)HWSZ);
    }

    if (t >= 64 && t < 96) {        // warp 2 computes the 15 moment sums
        int lane = t & 31;
        float acc[15];
        #pragma unroll
        for (int i = 0; i < 15; i++) acc[i] = 0.f;
        #pragma unroll
        for (int rep = 0; rep < 4; rep++) {
            int e = lane + rep * 32;
            float a, b;
            a = qw[e]; b = qb[e];
            acc[0] += a; acc[1] += b; acc[2] += a * a; acc[3] += a * b; acc[4] += b * b;
            a = kw[e]; b = kb[e];
            acc[5] += a; acc[6] += b; acc[7] += a * a; acc[8] += a * b; acc[9] += b * b;
            a = vw[e]; b = vb[e];
            acc[10] += a; acc[11] += b; acc[12] += a * a; acc[13] += a * b; acc[14] += b * b;
        }
        #pragma unroll
        for (int off = 16; off; off >>= 1)
            #pragma unroll
            for (int i = 0; i < 15; i++) acc[i] += __shfl_down_sync(0xffffffffu, acc[i], off);
        if (lane == 0) {
            const float inv = 1.0f / (float)E_DIM;
            #pragma unroll
            for (int gidx = 0; gidx < 3; gidx++) {
                float mw  = acc[gidx * 5 + 0] * inv;
                float mb  = acc[gidx * 5 + 1] * inv;
                s_stats[gidx * 5 + 0] = mw;
                s_stats[gidx * 5 + 1] = mb;
                s_stats[gidx * 5 + 2] = acc[gidx * 5 + 2] * inv - mw * mw;
                s_stats[gidx * 5 + 3] = acc[gidx * 5 + 3] * inv - mw * mb;
                s_stats[gidx * 5 + 4] = acc[gidx * 5 + 4] * inv - mb * mb;
            }
        }
    }
    __syncthreads();

    float qa  = s_stats[2];
    float qb2 = 2.0f * s_stats[3];
    float qc  = s_stats[4] + LN_EPS;
    if (blockIdx.x == 0 && t == 0) {
        g_qstat[0] = qa; g_qstat[1] = qb2; g_qstat[2] = qc;
    }

    // each thread computes 2 (head,module) coefficient entries
    {
        float mqw = s_stats[0],  mqb = s_stats[1];
        float mkw = s_stats[5],  mkb = s_stats[6];
        float Vkw = s_stats[7],  Ckwb = s_stats[8],  Vkb = s_stats[9];
        float mvw = s_stats[10], mvb = s_stats[11];
        float Vvw = s_stats[12], Cvwb = s_stats[13], Vvb = s_stats[14];
        const float cscale = rsqrtf((float)HDIM) * LOG2E;

        #pragma unroll
        for (int rep = 0; rep < 2; rep++) {
            int idx = t + rep * TAB_TPB;           // 0..255
            int h = idx >> 6, m = idx & 63;
            float p = s_pooled[m];
            float rk = rsqrtf(p * p * Vkw + 2.0f * p * Ckwb + Vkb + LN_EPS);
            float rv = rsqrtf(p * p * Vvw + 2.0f * p * Cvwb + Vvb + LN_EPS);

            float a1 = 0.f, a2 = 0.f, a3 = 0.f, w = 0.f;
            #pragma unroll 8
            for (int j = 0; j < HDIM; j++) {
                int e = h * HDIM + j;
                float4 kk = s_k[e];
                float4 vv = s_v[e];
                float4 qq = s_q[e];
                float ke = ((kk.x - mkw) * p + (kk.y - mkb)) * rk * kk.z + kk.w;
                float ve = ((vv.x - mvw) * p + (vv.y - mvb)) * rv * vv.z + vv.w;
                float uq = (qq.x - mqw) * qq.z;
                float tq = (qq.y - mqb) * qq.z;
                a1 = fmaf(uq, ke, a1);
                a2 = fmaf(tq, ke, a2);
                a3 = fmaf(qq.w, ke, a3);
                w  = fmaf(ve, s_ow[e], w);
            }
            float4 out4 = make_float4(a1 * cscale, a2 * cscale, a3 * cscale, w);
            sAB[idx] = out4;
            if (blockIdx.x == 0) g_AB[idx] = out4;
        }
    }
    __syncthreads();

    const float hstep = (XMAX - XMIN) / (float)(TABN - 1);
    float ob = outb[0];
    int base = blockIdx.x * (TAB_TPB - 1);          // blocks overlap by 1 node
    int i = base + t;
    if (i > TABN - 1) i = TABN - 1;                 // clamp (last block spills)
    float x = XMIN + (float)i * hstep;
    sF[t] = eval_F_impl(x, sAB, qa, qb2, qc, ob);
    __syncthreads();
    if (t < TAB_TPB - 1 && base + t < TABN)
        g_F2[base + t] = make_float2(sF[t], sF[t + 1]);
}

// ---------------- kernel 3: pointwise apply (lerp + gate) ----------------
__global__ __launch_bounds__(APPLY_TPB) void apply_kernel(
    const float* __restrict__ coeff, float* __restrict__ out,
    const float* __restrict__ gatew, const float* __restrict__ gateb,
    const float* __restrict__ outb)
{
    int tid = blockIdx.x * APPLY_TPB + threadIdx.x;
    const float4* cin = reinterpret_cast<const float4*>(coeff);
    float4* cout = reinterpret_cast<float4*>(out);
    // fold -log2e into gate affine so sigmoid = 1/(1+ex2(z'))
    float gw0 = __ldg(gatew) * -LOG2E;
    float gw1 = __ldg(gatew + 1) * -LOG2E;
    float gbv = __ldg(gateb) * -LOG2E;

    const float INVH  = (float)(TABN - 1) / (XMAX - XMIN);
    const float BIAS  = -XMIN * INVH;

    float4 xv[4];
    #pragma unroll
    for (int v = 0; v < 3; v++) xv[v] = cin[tid + v * APPLY_NT];
    bool has4 = (tid + 3 * APPLY_NT) < APPLY_NV4;
    if (has4) xv[3] = cin[tid + 3 * APPLY_NT];
    else      xv[3] = make_float4(0.f, 0.f, 0.f, 0.f);

    #pragma unroll
    for (int v = 0; v < 4; v++) {
        float xin[4] = {xv[v].x, xv[v].y, xv[v].z, xv[v].w};
        float res[4];
        #pragma unroll
        for (int j = 0; j < 4; j++) {
            float x = xin[j];
            float F;
            if (x >= XMIN && x <= XMAX) {
                float tpos = fmaf(x, INVH, BIAS);
                int i0 = __float2int_rd(tpos);
                if (i0 > TABN - 2) i0 = TABN - 2;
                float f = tpos - (float)i0;
                float2 p = g_F2[i0];
                F = fmaf(f, p.y - p.x, p.x);
            } else {
                F = eval_F_cold(x, g_qstat[0], g_qstat[1], g_qstat[2], __ldg(outb));
            }
            float z = fmaf(gw1, F, fmaf(gw0, x, gbv));
            float g = __fdividef(1.0f, 1.0f + fast_ex2(z));
            res[j] = fmaf(g, F - x, x);   // g*F + (1-g)*x
        }
        float4 ov = {res[0], res[1], res[2], res[3]};
        if (v < 3)      cout[tid + v * APPLY_NT] = ov;
        else if (has4)  cout[tid + 3 * APPLY_NT] = ov;
    }
}

// ---------------- launch ----------------
extern "C" void kernel_launch(void* const* d_in, const int* in_sizes, int n_in,
                              void* d_out, int out_size) {
    (void)in_sizes; (void)n_in; (void)out_size;
    const float* coeff = (const float*)d_in[0];
    const float* proto = (const float*)d_in[1];
    const float* qw    = (const float*)d_in[2];
    const float* qb    = (const float*)d_in[3];
    const float* qg    = (const float*)d_in[4];
    const float* qbeta = (const float*)d_in[5];
    const float* kw    = (const float*)d_in[6];
    const float* kb    = (const float*)d_in[7];
    const float* kg    = (const float*)d_in[8];
    const float* kbeta = (const float*)d_in[9];
    const float* vw    = (const float*)d_in[10];
    const float* vb    = (const float*)d_in[11];
    const float* vg    = (const float*)d_in[12];
    const float* vbeta = (const float*)d_in[13];
    const float* outw  = (const float*)d_in[14];
    const float* outb  = (const float*)d_in[15];
    const float* gatew = (const float*)d_in[16];
    const float* gateb = (const float*)d_in[17];
    float* out = (float*)d_out;

    pool_kernel<<<POOL_BLOCKS, POOL_TPB>>>(proto);
    table_kernel<<<TAB_BLOCKS, TAB_TPB>>>(qw, qb, qg, qbeta, kw, kb, kg, kbeta,
                                          vw, vb, vg, vbeta, outw, outb);
    apply_kernel<<<APPLY_BLOCKS, APPLY_TPB>>>(coeff, out, gatew, gateb, outb);
}

// round 5
// speedup vs baseline: 2.6227x; 1.0812x over previous
#include <cuda_runtime.h>
#include <math.h>

#define NM      64
#define A_DIM   8400
#define E_DIM   128
#define NHEAD   4
#define HDIM    32
#define HWSZ    25600      // 160*160
#define LN_EPS  1e-5f
#define LOG2E   1.4426950408889634f
#define TABN    8192
#define XMIN    -10.0f
#define XMAX    10.0f

#define POOL_BLOCKS 320     // 5 chunks per module, 1280 float4 each
#define POOL_TPB    256
#define TAB_TPB     128
#define TAB_BLOCKS  65      // 127 usable nodes per block (overlap by 1)

#define APPLY_BLOCKS 350
#define APPLY_TPB    384    // 350*384 = 134400 float4 = 537600 floats exactly

// ---------------- device scratch (no allocation allowed) ----------------
__device__ float  g_partial[POOL_BLOCKS];
__device__ float4 g_AB[NHEAD * NM];    // (A1,A2,A3,W); A* pre-scaled by log2e*scale
__device__ float  g_qstat[3];          // {Vw, 2*Cwb, Vb+eps} for queries
__device__ float2 g_F2[TABN];          // (F[i], F[i+1]) pairs

__device__ __forceinline__ float fast_ex2(float x) {
    float y; asm("ex2.approx.f32 %0, %1;" : "=f"(y) : "f"(x)); return y;
}

// ---------------- kernel 1: prototype pooling partial sums ----------------
__global__ __launch_bounds__(POOL_TPB, 1) void pool_kernel(const float* __restrict__ proto) {
    const float4* p4 = reinterpret_cast<const float4*>(proto) + (size_t)blockIdx.x * 1280;
    int t = threadIdx.x;
    float4 v0 = p4[t];
    float4 v1 = p4[t + 256];
    float4 v2 = p4[t + 512];
    float4 v3 = p4[t + 768];
    float4 v4 = p4[t + 1024];
    float s0 = (v0.x + v0.y) + (v0.z + v0.w);
    float s1 = (v1.x + v1.y) + (v1.z + v1.w);
    float s2 = (v2.x + v2.y) + (v2.z + v2.w);
    float s3 = (v3.x + v3.y) + (v3.z + v3.w);
    float s4 = (v4.x + v4.y) + (v4.z + v4.w);
    float sum = ((s0 + s1) + (s2 + s3)) + s4;
    #pragma unroll
    for (int off = 16; off; off >>= 1) sum += __shfl_down_sync(0xffffffffu, sum, off);
    __shared__ float wsum[8];
    if ((t & 31) == 0) wsum[t >> 5] = sum;
    __syncthreads();
    if (t < 8) {
        float v = wsum[t];
        #pragma unroll
        for (int off = 4; off; off >>= 1) v += __shfl_down_sync(0xffu, v, off);
        if (t == 0) g_partial[blockIdx.x] = v;
    }
}

// ---------------- shared evaluator: refined = F(x) ----------------
// AB holds (A1*log2e*scale, A2*log2e*scale, A3*log2e*scale, W)
__device__ __forceinline__ float eval_F_impl(float x, const float4* __restrict__ AB,
                                             float qa, float qb2, float qc, float out_b)
{
    float r = rsqrtf(fmaf(x, fmaf(qa, x, qb2), qc));
    float acc = out_b;
    #pragma unroll
    for (int h = 0; h < NHEAD; h++) {
        const float4* ABh = AB + h * NM;
        float s[NM];
        float mx = -1e30f;
        #pragma unroll
        for (int m = 0; m < NM; m++) {
            float4 ab = ABh[m];
            s[m] = fmaf(r, fmaf(x, ab.x, ab.y), ab.z);
            mx = fmaxf(mx, s[m]);
        }
        float se = 0.f, ws = 0.f;
        #pragma unroll
        for (int m = 0; m < NM; m++) {
            float4 ab = ABh[m];
            float e = fast_ex2(s[m] - mx);
            se += e;
            ws = fmaf(e, ab.w, ws);
        }
        acc += __fdividef(ws, se);
    }
    return acc;
}

__device__ __noinline__ float eval_F_cold(float x, float qa, float qb2, float qc, float out_b)
{
    return eval_F_impl(x, g_AB, qa, qb2, qc, out_b);
}

// ---------- kernel 2 (fused): per-block precompute + table slice ----------
__global__ __launch_bounds__(TAB_TPB) void table_kernel(
    const float* __restrict__ qw, const float* __restrict__ qb,
    const float* __restrict__ qg, const float* __restrict__ qbeta,
    const float* __restrict__ kw, const float* __restrict__ kb,
    const float* __restrict__ kg, const float* __restrict__ kbeta,
    const float* __restrict__ vw, const float* __restrict__ vb,
    const float* __restrict__ vg, const float* __restrict__ vbeta,
    const float* __restrict__ outw, const float* __restrict__ outb)
{
    __shared__ float  s_pooled[NM];
    __shared__ float  s_stats[15];   // q:{mw,mb,Vw,Cwb,Vb} k:{..} v:{..}
    __shared__ float4 s_k[E_DIM];    // (kw,kb,kg,kbeta)
    __shared__ float4 s_v[E_DIM];    // (vw,vb,vg,vbeta)
    __shared__ float4 s_q[E_DIM];    // (qw,qb,qg,qbeta)
    __shared__ float  s_ow[E_DIM];
    __shared__ float4 sAB[NHEAD * NM];
    __shared__ float  sF[TAB_TPB + 1];
    int t = threadIdx.x;

    // stage param tuples into shared (E = 128 = TPB)
    s_k[t] = make_float4(kw[t], kb[t], kg[t], kbeta[t]);
    s_v[t] = make_float4(vw[t], vb[t], vg[t], vbeta[t]);
    s_q[t] = make_float4(qw[t], qb[t], qg[t], qbeta[t]);
    s_ow[t] = outw[t];

    if (t < NM) {
        float s = 0.f;
        #pragma unroll
        for (int j = 0; j < 5; j++) s += g_partial[t * 5 + j];
        s_pooled[t] = s * (1.0f / (float)HWSZ);
    }

    if (t >= 64 && t < 96) {        // warp 2 computes the 15 moment sums
        int lane = t & 31;
        float acc[15];
        #pragma unroll
        for (int i = 0; i < 15; i++) acc[i] = 0.f;
        #pragma unroll
        for (int rep = 0; rep < 4; rep++) {
            int e = lane + rep * 32;
            float a, b;
            a = qw[e]; b = qb[e];
            acc[0] += a; acc[1] += b; acc[2] += a * a; acc[3] += a * b; acc[4] += b * b;
            a = kw[e]; b = kb[e];
            acc[5] += a; acc[6] += b; acc[7] += a * a; acc[8] += a * b; acc[9] += b * b;
            a = vw[e]; b = vb[e];
            acc[10] += a; acc[11] += b; acc[12] += a * a; acc[13] += a * b; acc[14] += b * b;
        }
        #pragma unroll
        for (int off = 16; off; off >>= 1)
            #pragma unroll
            for (int i = 0; i < 15; i++) acc[i] += __shfl_down_sync(0xffffffffu, acc[i], off);
        if (lane == 0) {
            const float inv = 1.0f / (float)E_DIM;
            #pragma unroll
            for (int gidx = 0; gidx < 3; gidx++) {
                float mw  = acc[gidx * 5 + 0] * inv;
                float mb  = acc[gidx * 5 + 1] * inv;
                s_stats[gidx * 5 + 0] = mw;
                s_stats[gidx * 5 + 1] = mb;
                s_stats[gidx * 5 + 2] = acc[gidx * 5 + 2] * inv - mw * mw;
                s_stats[gidx * 5 + 3] = acc[gidx * 5 + 3] * inv - mw * mb;
                s_stats[gidx * 5 + 4] = acc[gidx * 5 + 4] * inv - mb * mb;
            }
        }
    }
    __syncthreads();

    float qa  = s_stats[2];
    float qb2 = 2.0f * s_stats[3];
    float qc  = s_stats[4] + LN_EPS;
    if (blockIdx.x == 0 && t == 0) {
        g_qstat[0] = qa; g_qstat[1] = qb2; g_qstat[2] = qc;
    }

    // each thread computes 2 (head,module) coefficient entries
    {
        float mqw = s_stats[0],  mqb = s_stats[1];
        float mkw = s_stats[5],  mkb = s_stats[6];
        float Vkw = s_stats[7],  Ckwb = s_stats[8],  Vkb = s_stats[9];
        float mvw = s_stats[10], mvb = s_stats[11];
        float Vvw = s_stats[12], Cvwb = s_stats[13], Vvb = s_stats[14];
        const float cscale = rsqrtf((float)HDIM) * LOG2E;

        #pragma unroll
        for (int rep = 0; rep < 2; rep++) {
            int idx = t + rep * TAB_TPB;           // 0..255
            int h = idx >> 6, m = idx & 63;
            float p = s_pooled[m];
            float rk = rsqrtf(p * p * Vkw + 2.0f * p * Ckwb + Vkb + LN_EPS);
            float rv = rsqrtf(p * p * Vvw + 2.0f * p * Cvwb + Vvb + LN_EPS);

            float a1 = 0.f, a2 = 0.f, a3 = 0.f, w = 0.f;
            #pragma unroll 8
            for (int j = 0; j < HDIM; j++) {
                int e = h * HDIM + j;
                float4 kk = s_k[e];
                float4 vv = s_v[e];
                float4 qq = s_q[e];
                float ke = ((kk.x - mkw) * p + (kk.y - mkb)) * rk * kk.z + kk.w;
                float ve = ((vv.x - mvw) * p + (vv.y - mvb)) * rv * vv.z + vv.w;
                float uq = (qq.x - mqw) * qq.z;
                float tq = (qq.y - mqb) * qq.z;
                a1 = fmaf(uq, ke, a1);
                a2 = fmaf(tq, ke, a2);
                a3 = fmaf(qq.w, ke, a3);
                w  = fmaf(ve, s_ow[e], w);
            }
            float4 out4 = make_float4(a1 * cscale, a2 * cscale, a3 * cscale, w);
            sAB[idx] = out4;
            if (blockIdx.x == 0) g_AB[idx] = out4;
        }
    }
    __syncthreads();

    const float hstep = (XMAX - XMIN) / (float)(TABN - 1);
    float ob = outb[0];
    int base = blockIdx.x * (TAB_TPB - 1);          // blocks overlap by 1 node
    int i = base + t;
    if (i > TABN - 1) i = TABN - 1;                 // clamp (last block spills)
    float x = XMIN + (float)i * hstep;
    sF[t] = eval_F_impl(x, sAB, qa, qb2, qc, ob);
    __syncthreads();
    if (t < TAB_TPB - 1 && base + t < TABN)
        g_F2[base + t] = make_float2(sF[t], sF[t + 1]);
}

// ---------------- kernel 3: pointwise apply (lerp + gate) ----------------
__global__ __launch_bounds__(APPLY_TPB) void apply_kernel(
    const float* __restrict__ coeff, float* __restrict__ out,
    const float* __restrict__ gatew, const float* __restrict__ gateb,
    const float* __restrict__ outb)
{
    int tid = blockIdx.x * APPLY_TPB + threadIdx.x;   // 0..134399, one float4 each
    const float4* cin = reinterpret_cast<const float4*>(coeff);
    float4* cout = reinterpret_cast<float4*>(out);
    // fold -log2e into gate affine so sigmoid = 1/(1+ex2(z'))
    float gw0 = __ldg(gatew) * -LOG2E;
    float gw1 = __ldg(gatew + 1) * -LOG2E;
    float gbv = __ldg(gateb) * -LOG2E;

    const float INVH  = (float)(TABN - 1) / (XMAX - XMIN);
    const float BIAS  = -XMIN * INVH;

    float4 xv = cin[tid];
    float xin[4] = {xv.x, xv.y, xv.z, xv.w};

    // issue all 4 table gathers up front (independent -> MLP)
    float2 p[4];
    float fpos[4];
    bool inr[4];
    #pragma unroll
    for (int j = 0; j < 4; j++) {
        float x = xin[j];
        inr[j] = (x >= XMIN) && (x <= XMAX);
        float tpos = fmaf(x, INVH, BIAS);
        int i0 = __float2int_rd(tpos);
        i0 = (i0 < 0) ? 0 : ((i0 > TABN - 2) ? TABN - 2 : i0);
        fpos[j] = tpos - (float)i0;
        p[j] = g_F2[i0];
    }

    float res[4];
    #pragma unroll
    for (int j = 0; j < 4; j++) {
        float x = xin[j];
        float F;
        if (inr[j]) {
            F = fmaf(fpos[j], p[j].y - p[j].x, p[j].x);
        } else {
            F = eval_F_cold(x, g_qstat[0], g_qstat[1], g_qstat[2], __ldg(outb));
        }
        float z = fmaf(gw1, F, fmaf(gw0, x, gbv));
        float g = __fdividef(1.0f, 1.0f + fast_ex2(z));
        res[j] = fmaf(g, F - x, x);   // g*F + (1-g)*x
    }
    cout[tid] = make_float4(res[0], res[1], res[2], res[3]);
}

// ---------------- launch ----------------
extern "C" void kernel_launch(void* const* d_in, const int* in_sizes, int n_in,
                              void* d_out, int out_size) {
    (void)in_sizes; (void)n_in; (void)out_size;
    const float* coeff = (const float*)d_in[0];
    const float* proto = (const float*)d_in[1];
    const float* qw    = (const float*)d_in[2];
    const float* qb    = (const float*)d_in[3];
    const float* qg    = (const float*)d_in[4];
    const float* qbeta = (const float*)d_in[5];
    const float* kw    = (const float*)d_in[6];
    const float* kb    = (const float*)d_in[7];
    const float* kg    = (const float*)d_in[8];
    const float* kbeta = (const float*)d_in[9];
    const float* vw    = (const float*)d_in[10];
    const float* vb    = (const float*)d_in[11];
    const float* vg    = (const float*)d_in[12];
    const float* vbeta = (const float*)d_in[13];
    const float* outw  = (const float*)d_in[14];
    const float* outb  = (const float*)d_in[15];
    const float* gatew = (const float*)d_in[16];
    const float* gateb = (const float*)d_in[17];
    float* out = (float*)d_out;

    pool_kernel<<<POOL_BLOCKS, POOL_TPB>>>(proto);
    table_kernel<<<TAB_BLOCKS, TAB_TPB>>>(qw, qb, qg, qbeta, kw, kb, kg, kbeta,
                                          vw, vb, vg, vbeta, outw, outb);
    apply_kernel<<<APPLY_BLOCKS, APPLY_TPB>>>(coeff, out, gatew, gateb, outb);
}